// round 6
// baseline (speedup 1.0000x reference)
#include <cuda_runtime.h>
#include <cuda_bf16.h>

// FrequencyAdaptiveNormSimple, packed-f32x2 version.
// out = sum_w softmax(alpha)[h,w] * (x - mu_w)/max(sd_w,1e-4), windows (5,10,20),
// replicate-padded stats for t < w-1. B=32, T=2048, H=512 fp32.
// Each thread handles 2 adjacent features; window sums, updates and variance run
// on fma.rn.f32x2 / add.rn.f32x2 / mul.rn.f32x2; only clamp+rsqrt+blend scalar.

constexpr int Bc  = 32;
constexpr int Tc  = 2048;
constexpr int Hc  = 512;
constexpr int THR = 64;           // threads per block
constexpr int FPB = 2 * THR;      // features per block = 128
constexpr int TCc = 128;          // time chunk per block
constexpr int NCH = Tc / TCc;     // 16
constexpr int NHB = Hc / FPB;     // 4

typedef unsigned long long u64;

static __device__ __forceinline__ u64 f2pack(float lo, float hi) {
    u64 r; asm("mov.b64 %0, {%1,%2};" : "=l"(r) : "f"(lo), "f"(hi)); return r;
}
static __device__ __forceinline__ void f2unpack(u64 v, float& lo, float& hi) {
    asm("mov.b64 {%0,%1}, %2;" : "=f"(lo), "=f"(hi) : "l"(v));
}
static __device__ __forceinline__ u64 f2fma(u64 a, u64 b, u64 c) {
    u64 d; asm("fma.rn.f32x2 %0, %1, %2, %3;" : "=l"(d) : "l"(a), "l"(b), "l"(c)); return d;
}
static __device__ __forceinline__ u64 f2add(u64 a, u64 b) {
    u64 d; asm("add.rn.f32x2 %0, %1, %2;" : "=l"(d) : "l"(a), "l"(b)); return d;
}
static __device__ __forceinline__ u64 f2mul(u64 a, u64 b) {
    u64 d; asm("mul.rn.f32x2 %0, %1, %2;" : "=l"(d) : "l"(a), "l"(b)); return d;
}
static __device__ __forceinline__ float rsq(float v) {
    float r; asm("rsqrt.approx.f32 %0, %1;" : "=f"(r) : "f"(v)); return r;
}

// scalar znorm for the edge (t < 20) path only
template <int W>
static __device__ __forceinline__ float zc(float xv, float s, float q, float al) {
    const float c1   = 1.0f / (float)(W - 1);
    const float c2   = 1.0f / ((float)W * (float)(W - 1));
    const float invW = 1.0f / (float)W;
    float var   = q * c1 - (s * c2) * s;
    float invsd = rsq(fmaxf(var, 1e-8f));
    return (xv - s * invW) * (al * invsd);
}

// packed window update: s += v - l ; q += v*v - l*l
#define WIN_UPD(S, Q, L, V, V2)                        \
    S = f2add(S, f2fma((L), NEG1, (V)));               \
    Q = f2fma((L), f2mul((L), NEG1), f2add(Q, (V2)));

// packed variance core + scalar clamp/rsqrt/blend.
// var0 = q - s*s/W (clamped at (W-1)*1e-8), m = v - s/W,
// contribution = m * (al*sqrt(W-1)) * rsqrt(var0)
#define WIN_NRM(S, Q, NIW, ALO, AHI, EPSW, V, OLO, OHI) {     \
    u64 _t2 = f2mul((S), (NIW));                              \
    u64 _m  = f2fma((S), (NIW), (V));                         \
    u64 _v0 = f2fma(_t2, (S), (Q));                           \
    float _vl, _vh, _ml, _mh;                                 \
    f2unpack(_v0, _vl, _vh); f2unpack(_m, _ml, _mh);          \
    OLO = fmaf(_ml, (ALO) * rsq(fmaxf(_vl, (EPSW))), OLO);    \
    OHI = fmaf(_mh, (AHI) * rsq(fmaxf(_vh, (EPSW))), OHI); }

// one steady-state timestep; J is a literal so ring indices fold to constants
#define STEP(J, V, OPTR) {                                          \
    u64 _v  = (V);                                                  \
    u64 _v2 = f2mul(_v, _v);                                        \
    u64 _l20 = r[(J)];                                              \
    u64 _l10 = r[((J) + 10) % 20];                                  \
    u64 _l5  = r[((J) + 15) % 20];                                  \
    WIN_UPD(s20, q20, _l20, _v, _v2);                               \
    WIN_UPD(s10, q10, _l10, _v, _v2);                               \
    WIN_UPD(s5,  q5,  _l5,  _v, _v2);                               \
    r[(J)] = _v;                                                    \
    float _ol = 0.0f, _oh = 0.0f;                                   \
    WIN_NRM(s5,  q5,  NIW5,  a5l,  a5h,  4e-8f,  _v, _ol, _oh);     \
    WIN_NRM(s10, q10, NIW10, a10l, a10h, 9e-8f,  _v, _ol, _oh);     \
    WIN_NRM(s20, q20, NIW20, a20l, a20h, 19e-8f, _v, _ol, _oh);     \
    __stcs((float2*)((OPTR) + (J) * Hc), make_float2(_ol, _oh)); }

__global__ __launch_bounds__(THR)
void fan_kernel(const float* __restrict__ x,
                const float* __restrict__ alpha,
                float* __restrict__ out)
{
    const int tid   = threadIdx.x;
    int blk         = blockIdx.x;
    const int chunk = blk % NCH; blk /= NCH;
    const int hb    = blk % NHB; blk /= NHB;
    const int b     = blk;
    const int hbase = hb * FPB + 2 * tid;       // even -> float2 aligned

    const float* xp = x   + (size_t)b * Tc * Hc + hbase;
    float*       op = out + (size_t)b * Tc * Hc + hbase;

    // softmax over 3 window weights, both lanes
    float al5l, al10l, al20l, al5h, al10h, al20h;
    {
        float a0 = __ldg(&alpha[hbase * 3 + 0]);
        float a1 = __ldg(&alpha[hbase * 3 + 1]);
        float a2 = __ldg(&alpha[hbase * 3 + 2]);
        float mx = fmaxf(a0, fmaxf(a1, a2));
        float e0 = __expf(a0 - mx), e1 = __expf(a1 - mx), e2 = __expf(a2 - mx);
        float ai = 1.0f / (e0 + e1 + e2);
        al5l = e0 * ai; al10l = e1 * ai; al20l = e2 * ai;
        a0 = __ldg(&alpha[(hbase + 1) * 3 + 0]);
        a1 = __ldg(&alpha[(hbase + 1) * 3 + 1]);
        a2 = __ldg(&alpha[(hbase + 1) * 3 + 2]);
        mx = fmaxf(a0, fmaxf(a1, a2));
        e0 = __expf(a0 - mx); e1 = __expf(a1 - mx); e2 = __expf(a2 - mx);
        ai = 1.0f / (e0 + e1 + e2);
        al5h = e0 * ai; al10h = e1 * ai; al20h = e2 * ai;
    }
    // scaled weights: fold sqrt(W-1) (from var0 clamp transform) into alpha
    const float a5l  = al5l  * 2.0f,          a5h  = al5h  * 2.0f;
    const float a10l = al10l * 3.0f,          a10h = al10h * 3.0f;
    const float a20l = al20l * 4.35889894354f, a20h = al20h * 4.35889894354f; // sqrt(19)

    const u64 NEG1  = f2pack(-1.0f,  -1.0f);
    const u64 NIW5  = f2pack(-0.2f,  -0.2f);
    const u64 NIW10 = f2pack(-0.1f,  -0.1f);
    const u64 NIW20 = f2pack(-0.05f, -0.05f);

    u64 r[20];                       // packed ring of last 20 x pairs
    u64 s5, q5, s10, q10, s20, q20;
    int tbeg;

    if (chunk == 0) {
        // ---- edge: t = 0..19, replicate-padded stats (scalar per lane) ----
        #pragma unroll
        for (int t = 0; t < 20; t++) {
            float2 w = __ldg((const float2*)(xp + t * Hc));
            r[t] = f2pack(w.x, w.y);
        }
        #pragma unroll
        for (int lane = 0; lane < 2; lane++) {
            float rv[20];
            #pragma unroll
            for (int t = 0; t < 20; t++) {
                float lo, hi; f2unpack(r[t], lo, hi);
                rv[t] = lane ? hi : lo;
            }
            const float w5  = lane ? al5h  : al5l;
            const float w10 = lane ? al10h : al10l;
            const float w20 = lane ? al20h : al20l;
            float ob[20];
            #pragma unroll
            for (int t = 0; t < 20; t++) ob[t] = 0.0f;
            // w = 5
            {
                float s = 0.f, q = 0.f;
                #pragma unroll
                for (int t = 0; t < 20; t++) {
                    float v = rv[t];
                    s += v; q += v * v;
                    if (t >= 5) { float l = rv[t - 5]; s -= l; q -= l * l; }
                    if (t == 4) {
                        #pragma unroll
                        for (int tp = 0; tp <= 4; tp++) ob[tp] += zc<5>(rv[tp], s, q, w5);
                    } else if (t > 4) {
                        ob[t] += zc<5>(v, s, q, w5);
                    }
                }
            }
            // w = 10
            {
                float s = 0.f, q = 0.f;
                #pragma unroll
                for (int t = 0; t < 20; t++) {
                    float v = rv[t];
                    s += v; q += v * v;
                    if (t >= 10) { float l = rv[t - 10]; s -= l; q -= l * l; }
                    if (t == 9) {
                        #pragma unroll
                        for (int tp = 0; tp <= 9; tp++) ob[tp] += zc<10>(rv[tp], s, q, w10);
                    } else if (t > 9) {
                        ob[t] += zc<10>(v, s, q, w10);
                    }
                }
            }
            // w = 20
            {
                float s = 0.f, q = 0.f;
                #pragma unroll
                for (int t = 0; t < 20; t++) { float v = rv[t]; s += v; q += v * v; }
                #pragma unroll
                for (int tp = 0; tp < 20; tp++) ob[tp] += zc<20>(rv[tp], s, q, w20);
            }
            float* os = op + lane;
            #pragma unroll
            for (int t = 0; t < 20; t++) os[t * Hc] = ob[t];
        }
        // packed prefix sums from ring
        s5 = q5 = s10 = q10 = s20 = q20 = 0ULL;
        #pragma unroll
        for (int i = 0; i < 20; i++) {
            u64 v = r[i], v2 = f2mul(v, v);
            s20 = f2add(s20, v); q20 = f2add(q20, v2);
            if (i >= 10) { s10 = f2add(s10, v); q10 = f2add(q10, v2); }
            if (i >= 15) { s5  = f2add(s5,  v); q5  = f2add(q5,  v2); }
        }
        tbeg = 20;
    } else {
        // ---- halo warmup: ring <- x[t0-20 .. t0-1] ----
        const int t0 = chunk * TCc;
        const float* ph = xp + (size_t)(t0 - 20) * Hc;
        #pragma unroll
        for (int i = 0; i < 20; i++) {
            float2 w = __ldg((const float2*)(ph + i * Hc));
            r[i] = f2pack(w.x, w.y);
        }
        s5 = q5 = s10 = q10 = s20 = q20 = 0ULL;
        #pragma unroll
        for (int i = 0; i < 20; i++) {
            u64 v = r[i], v2 = f2mul(v, v);
            s20 = f2add(s20, v); q20 = f2add(q20, v2);
            if (i >= 10) { s10 = f2add(s10, v); q10 = f2add(q10, v2); }
            if (i >= 15) { s5  = f2add(s5,  v); q5  = f2add(q5,  v2); }
        }
        tbeg = t0;
    }

    const int tend = chunk * TCc + TCc;
    int tb = tbeg;

    // ---- steady state: 20-step blocks, ring slots are compile-time ----
    for (; tb + 20 <= tend; tb += 20) {
        const float* p = xp + (size_t)tb * Hc;
        float*       o = op + (size_t)tb * Hc;
        u64 xv[10];
        #pragma unroll
        for (int j = 0; j < 10; j++) {
            float2 w = __ldg((const float2*)(p + j * Hc));
            xv[j] = f2pack(w.x, w.y);
        }
        STEP(0, xv[0], o); STEP(1, xv[1], o); STEP(2, xv[2], o); STEP(3, xv[3], o);
        STEP(4, xv[4], o); STEP(5, xv[5], o); STEP(6, xv[6], o); STEP(7, xv[7], o);
        STEP(8, xv[8], o); STEP(9, xv[9], o);
        #pragma unroll
        for (int j = 0; j < 10; j++) {
            float2 w = __ldg((const float2*)(p + (j + 10) * Hc));
            xv[j] = f2pack(w.x, w.y);
        }
        STEP(10, xv[0], o); STEP(11, xv[1], o); STEP(12, xv[2], o); STEP(13, xv[3], o);
        STEP(14, xv[4], o); STEP(15, xv[5], o); STEP(16, xv[6], o); STEP(17, xv[7], o);
        STEP(18, xv[8], o); STEP(19, xv[9], o);
    }

    // ---- fixed 8-step tail ((TCc-20) % 20 == (TCc % 20) == 8) ----
    {
        const float* p = xp + (size_t)tb * Hc;
        float*       o = op + (size_t)tb * Hc;
        u64 xv[8];
        #pragma unroll
        for (int j = 0; j < 8; j++) {
            float2 w = __ldg((const float2*)(p + j * Hc));
            xv[j] = f2pack(w.x, w.y);
        }
        STEP(0, xv[0], o); STEP(1, xv[1], o); STEP(2, xv[2], o); STEP(3, xv[3], o);
        STEP(4, xv[4], o); STEP(5, xv[5], o); STEP(6, xv[6], o); STEP(7, xv[7], o);
    }
}

extern "C" void kernel_launch(void* const* d_in, const int* in_sizes, int n_in,
                              void* d_out, int out_size) {
    const float* x     = (const float*)d_in[0];
    const float* alpha = (const float*)d_in[1];
    float*       out   = (float*)d_out;
    dim3 grid(Bc * NHB * NCH);   // 32 * 4 * 16 = 2048 blocks
    dim3 block(THR);             // 64 threads
    fan_kernel<<<grid, block>>>(x, alpha, out);
}